// round 4
// baseline (speedup 1.0000x reference)
#include <cuda_runtime.h>
#include <cstdint>

// Problem shape (fixed by setup_inputs)
#define BB 64
#define SS 8192
#define EE 32
#define HH 64

typedef unsigned long long u64;

// ---------------- f32x2 helpers (Blackwell packed fp32) ----------------
__device__ __forceinline__ u64 pack2(float x, float y) {
    u64 r; asm("mov.b64 %0, {%1, %2};" : "=l"(r) : "f"(x), "f"(y)); return r;
}
__device__ __forceinline__ u64 dup2(float x) {
    u64 r; asm("mov.b64 %0, {%1, %1};" : "=l"(r) : "f"(x)); return r;
}
__device__ __forceinline__ void unpack2(u64 v, float& x, float& y) {
    asm("mov.b64 {%0, %1}, %2;" : "=f"(x), "=f"(y) : "l"(v));
}
__device__ __forceinline__ u64 ffma2(u64 a, u64 b, u64 c) {
    u64 d; asm("fma.rn.f32x2 %0, %1, %2, %3;" : "=l"(d) : "l"(a), "l"(b), "l"(c)); return d;
}
__device__ __forceinline__ float silu_f(float v) {
    return v / (1.0f + __expf(-v));
}

// ---------------- scratch (static device memory; no allocations) ----------------
__device__ float g_q[(size_t)BB * SS * EE];     // 64 MB intermediate q = silu(x@Qw^T)
__device__ float g_partial[BB * 64 * EE];       // per-(b, block) partial sum of squares
__device__ float g_rnorm[BB * EE];              // 1 / max(||q[:,f]||, eps)

// =======================================================================
// K1: q = silu(x @ Qw^T), 128-row tile, 128 threads, 4x8 register tile.
// Emits deterministic per-block partial sum-of-squares per column f.
// grid (64, 64). launch_bounds caps regs -> 6 blocks/SM (24 warps).
// =======================================================================
__global__ __launch_bounds__(128, 6) void k1_proj(const float* __restrict__ x,
                                                  const float* __restrict__ Qw) {
    __shared__ __align__(16) float xs[128][36];   // padded rows
    __shared__ __align__(16) u64   ws[32][16];    // ws[e][fpair]
    __shared__ float red[32][33];

    const int tid = threadIdx.x;
    const int b   = blockIdx.y;
    const int blk = blockIdx.x;
    const size_t base = ((size_t)b * SS + (size_t)blk * 128) * EE;

    // stage x tile (128 x 32 floats = 1024 float4)
    const float4* xsrc = (const float4*)(x + base);
#pragma unroll
    for (int i = 0; i < 8; i++) {
        int idx = tid + i * 128;
        *(float4*)&xs[idx >> 3][(idx & 7) * 4] = xsrc[idx];
    }
    // stage Qw as pairs along the output dim f
#pragma unroll
    for (int j = 0; j < 4; j++) {
        int i = tid + j * 128;
        int e = i >> 4, p = i & 15;
        ws[e][p] = pack2(Qw[(2 * p) * EE + e], Qw[(2 * p + 1) * EE + e]);
    }
    __syncthreads();

    const int rg = tid >> 2;   // 32 row-groups, rows rg + 32*r, r<4
    const int cg = tid & 3;    // 4 col-groups, cols 8*cg .. 8*cg+7

    u64 acc[4][4];
#pragma unroll
    for (int r = 0; r < 4; r++)
#pragma unroll
        for (int p = 0; p < 4; p++) acc[r][p] = 0ull;

#pragma unroll
    for (int k4 = 0; k4 < 8; k4++) {
        float xf[4][4];
#pragma unroll
        for (int r = 0; r < 4; r++)
            *(float4*)xf[r] = *(const float4*)&xs[rg + 32 * r][k4 * 4];
#pragma unroll
        for (int kk = 0; kk < 4; kk++) {
            int k = k4 * 4 + kk;
            ulonglong2 wa = *(const ulonglong2*)&ws[k][cg * 4];
            ulonglong2 wb = *(const ulonglong2*)&ws[k][cg * 4 + 2];
#pragma unroll
            for (int r = 0; r < 4; r++) {
                u64 xd = dup2(xf[r][kk]);
                acc[r][0] = ffma2(xd, wa.x, acc[r][0]);
                acc[r][1] = ffma2(xd, wa.y, acc[r][1]);
                acc[r][2] = ffma2(xd, wb.x, acc[r][2]);
                acc[r][3] = ffma2(xd, wb.y, acc[r][3]);
            }
        }
    }

    // epilogue: silu, store q, accumulate sum of squares per column
    float part[8];
#pragma unroll
    for (int c = 0; c < 8; c++) part[c] = 0.0f;

#pragma unroll
    for (int r = 0; r < 4; r++) {
        float v[8];
#pragma unroll
        for (int p = 0; p < 4; p++) unpack2(acc[r][p], v[2 * p], v[2 * p + 1]);
#pragma unroll
        for (int c = 0; c < 8; c++) {
            float s = silu_f(v[c]);
            v[c] = s;
            part[c] = fmaf(s, s, part[c]);
        }
        int row = rg + 32 * r;
        float* dst = g_q + base + (size_t)row * EE + cg * 8;
        *(float4*)dst       = make_float4(v[0], v[1], v[2], v[3]);
        *(float4*)(dst + 4) = make_float4(v[4], v[5], v[6], v[7]);
    }
#pragma unroll
    for (int c = 0; c < 8; c++) red[rg][cg * 8 + c] = part[c];
    __syncthreads();

    if (tid < 32) {
        float s = 0.0f;
#pragma unroll
        for (int i = 0; i < 32; i++) s += red[i][tid];
        g_partial[(b * 64 + blk) * EE + tid] = s;
    }
}

// =======================================================================
// K2: reduce 64 block partials -> rnorm. grid 64, block 32. Deterministic.
// =======================================================================
__global__ void k2_norm() {
    const int b = blockIdx.x;
    const int f = threadIdx.x;
    float s = 0.0f;
#pragma unroll
    for (int i = 0; i < 64; i++) s += g_partial[(b * 64 + i) * EE + f];
    g_rnorm[b * EE + f] = 1.0f / fmaxf(sqrtf(s), 1e-12f);
}

// =======================================================================
// K3: h = silu(q @ (rnorm o W1)^T + b1); out = h @ W2^T + b2
// 128-row tile, 256 threads. Stage1: 4x8 tile; Stage2: 4x4 tile.
// rnorm folded into W1 at staging. grid (64, 64), 70016 B dynamic smem.
// launch_bounds caps regs -> 3 blocks/SM (24 warps; 3 x 70KB smem fits).
// =======================================================================
__global__ __launch_bounds__(256, 3) void k3_mlp(const float* __restrict__ W1,
                                                 const float* __restrict__ b1,
                                                 const float* __restrict__ W2,
                                                 const float* __restrict__ b2,
                                                 float* __restrict__ out) {
    extern __shared__ __align__(16) char sm[];
    float (*qs)[36]  = (float (*)[36])(sm);                // 128*36*4  = 18432
    float (*hs)[68]  = (float (*)[68])(sm + 18432);        // 128*68*4  = 34816
    u64   (*w1s)[32] = (u64 (*)[32])(sm + 53248);          // [e][hpair] 8192
    u64   (*w2s)[16] = (u64 (*)[16])(sm + 61440);          // [h][epair] 8192
    u64* b1s = (u64*)(sm + 69632);                         // 256
    u64* b2s = (u64*)(sm + 69888);                         // 128 -> total 70016

    const int tid = threadIdx.x;
    const int b   = blockIdx.y;
    const int blk = blockIdx.x;
    const size_t base = ((size_t)b * SS + (size_t)blk * 128) * EE;

    // --- stage q tile (128 x 32 = 1024 float4) ---
    const float4* qsrc = (const float4*)(g_q + base);
#pragma unroll
    for (int i = 0; i < 4; i++) {
        int idx = tid + i * 256;
        *(float4*)&qs[idx >> 3][(idx & 7) * 4] = qsrc[idx];
    }
    // --- stage W1 * rnorm as pairs along h ---
    const float* W1b = W1 + (size_t)b * HH * EE;
    const float* rn  = g_rnorm + b * EE;
#pragma unroll
    for (int j = 0; j < 4; j++) {
        int i = tid + j * 256;         // 0..1023
        int e = i >> 5, hp = i & 31;
        float r = rn[e];
        w1s[e][hp] = pack2(W1b[(2 * hp) * EE + e] * r, W1b[(2 * hp + 1) * EE + e] * r);
    }
    // --- stage W2 as pairs along e ---
    const float* W2b = W2 + (size_t)b * EE * HH;
#pragma unroll
    for (int j = 0; j < 4; j++) {
        int i = tid + j * 256;
        int h = i >> 4, ep = i & 15;
        w2s[h][ep] = pack2(W2b[(2 * ep) * HH + h], W2b[(2 * ep + 1) * HH + h]);
    }
    if (tid < 32) b1s[tid] = pack2(b1[b * HH + 2 * tid], b1[b * HH + 2 * tid + 1]);
    if (tid < 16) b2s[tid] = pack2(b2[b * EE + 2 * tid], b2[b * EE + 2 * tid + 1]);
    __syncthreads();

    // ---------------- stage 1: h tile (128 x 64) ----------------
    {
        const int rg = tid >> 3;   // 32 row-groups, rows rg + 32*r, r<4
        const int cg = tid & 7;    // 8 col-groups, h cols 8*cg .. 8*cg+7
        u64 acc[4][4];
#pragma unroll
        for (int r = 0; r < 4; r++)
#pragma unroll
            for (int p = 0; p < 4; p++) acc[r][p] = b1s[cg * 4 + p];

#pragma unroll
        for (int k4 = 0; k4 < 8; k4++) {
            float xf[4][4];
#pragma unroll
            for (int r = 0; r < 4; r++)
                *(float4*)xf[r] = *(const float4*)&qs[rg + 32 * r][k4 * 4];
#pragma unroll
            for (int kk = 0; kk < 4; kk++) {
                int k = k4 * 4 + kk;
                ulonglong2 wa = *(const ulonglong2*)&w1s[k][cg * 4];
                ulonglong2 wb = *(const ulonglong2*)&w1s[k][cg * 4 + 2];
#pragma unroll
                for (int r = 0; r < 4; r++) {
                    u64 xd = dup2(xf[r][kk]);
                    acc[r][0] = ffma2(xd, wa.x, acc[r][0]);
                    acc[r][1] = ffma2(xd, wa.y, acc[r][1]);
                    acc[r][2] = ffma2(xd, wb.x, acc[r][2]);
                    acc[r][3] = ffma2(xd, wb.y, acc[r][3]);
                }
            }
        }
#pragma unroll
        for (int r = 0; r < 4; r++) {
            float v[8];
#pragma unroll
            for (int p = 0; p < 4; p++) unpack2(acc[r][p], v[2 * p], v[2 * p + 1]);
#pragma unroll
            for (int c = 0; c < 8; c++) v[c] = silu_f(v[c]);
            int row = rg + 32 * r;
            *(float4*)&hs[row][cg * 8]     = make_float4(v[0], v[1], v[2], v[3]);
            *(float4*)&hs[row][cg * 8 + 4] = make_float4(v[4], v[5], v[6], v[7]);
        }
    }
    __syncthreads();

    // ---------------- stage 2: out tile (128 x 32) ----------------
    {
        const int rg = tid >> 3;   // 32 row-groups, rows rg + 32*r, r<4
        const int cg = tid & 7;    // 8 col-groups, e cols 4*cg .. 4*cg+3
        u64 acc[4][2];
#pragma unroll
        for (int r = 0; r < 4; r++) {
            acc[r][0] = b2s[cg * 2];
            acc[r][1] = b2s[cg * 2 + 1];
        }

#pragma unroll
        for (int k4 = 0; k4 < 16; k4++) {
            float xf[4][4];
#pragma unroll
            for (int r = 0; r < 4; r++)
                *(float4*)xf[r] = *(const float4*)&hs[rg + 32 * r][k4 * 4];
#pragma unroll
            for (int kk = 0; kk < 4; kk++) {
                int k = k4 * 4 + kk;
                ulonglong2 w = *(const ulonglong2*)&w2s[k][cg * 2];
#pragma unroll
                for (int r = 0; r < 4; r++) {
                    u64 xd = dup2(xf[r][kk]);
                    acc[r][0] = ffma2(xd, w.x, acc[r][0]);
                    acc[r][1] = ffma2(xd, w.y, acc[r][1]);
                }
            }
        }
#pragma unroll
        for (int r = 0; r < 4; r++) {
            float v[4];
            unpack2(acc[r][0], v[0], v[1]);
            unpack2(acc[r][1], v[2], v[3]);
            int row = rg + 32 * r;
            *(float4*)(out + base + (size_t)row * EE + cg * 4) =
                make_float4(v[0], v[1], v[2], v[3]);
        }
    }
}

// =======================================================================
extern "C" void kernel_launch(void* const* d_in, const int* in_sizes, int n_in,
                              void* d_out, int out_size) {
    const float* x  = (const float*)d_in[0];
    const float* Qw = (const float*)d_in[1];
    const float* W1 = (const float*)d_in[2];
    const float* b1 = (const float*)d_in[3];
    const float* W2 = (const float*)d_in[4];
    const float* b2 = (const float*)d_in[5];
    float* out = (float*)d_out;

    // host-side attribute set; runs during capture only
    cudaFuncSetAttribute(k3_mlp, cudaFuncAttributeMaxDynamicSharedMemorySize, 70016);

    k1_proj<<<dim3(SS / 128, BB), 128>>>(x, Qw);
    k2_norm<<<BB, 32>>>();
    k3_mlp<<<dim3(SS / 128, BB), 256, 70016>>>(W1, b1, W2, b2, out);
}

// round 10
// speedup vs baseline: 1.1272x; 1.1272x over previous
#include <cuda_runtime.h>
#include <cstdint>

// Problem shape (fixed by setup_inputs)
#define BB 64
#define SS 8192
#define EE 32
#define HH 64

typedef unsigned long long u64;

// ---------------- f32x2 helpers (Blackwell packed fp32) ----------------
__device__ __forceinline__ u64 pack2(float x, float y) {
    u64 r; asm("mov.b64 %0, {%1, %2};" : "=l"(r) : "f"(x), "f"(y)); return r;
}
__device__ __forceinline__ u64 dup2(float x) {
    u64 r; asm("mov.b64 %0, {%1, %1};" : "=l"(r) : "f"(x)); return r;
}
__device__ __forceinline__ void unpack2(u64 v, float& x, float& y) {
    asm("mov.b64 {%0, %1}, %2;" : "=f"(x), "=f"(y) : "l"(v));
}
__device__ __forceinline__ u64 ffma2(u64 a, u64 b, u64 c) {
    u64 d; asm("fma.rn.f32x2 %0, %1, %2, %3;" : "=l"(d) : "l"(a), "l"(b), "l"(c)); return d;
}
__device__ __forceinline__ float silu_f(float v) {
    return v / (1.0f + __expf(-v));
}

// ---------------- scratch (static device memory; no allocations) ----------------
__device__ float g_q[(size_t)BB * SS * EE];     // 64 MB intermediate q = silu(x@Qw^T)
__device__ float g_partial[BB * 64 * EE];       // per-(b, block) partial sum of squares
__device__ float g_rnorm[BB * EE];              // 1 / max(||q[:,f]||, eps)

// =======================================================================
// K1 (unchanged from R4, proven 42.7us): q = silu(x @ Qw^T).
// 128-row tile, 128 threads, 4x8 register tile, 6 blocks/SM.
// Emits per-block partial sum-of-squares. grid (64, 64).
// =======================================================================
__global__ __launch_bounds__(128, 6) void k1_proj(const float* __restrict__ x,
                                                  const float* __restrict__ Qw) {
    __shared__ __align__(16) float xs[128][36];
    __shared__ __align__(16) u64   ws[32][16];
    __shared__ float red[32][33];

    const int tid = threadIdx.x;
    const int b   = blockIdx.y;
    const int blk = blockIdx.x;
    const size_t base = ((size_t)b * SS + (size_t)blk * 128) * EE;

    const float4* xsrc = (const float4*)(x + base);
#pragma unroll
    for (int i = 0; i < 8; i++) {
        int idx = tid + i * 128;
        *(float4*)&xs[idx >> 3][(idx & 7) * 4] = xsrc[idx];
    }
#pragma unroll
    for (int j = 0; j < 4; j++) {
        int i = tid + j * 128;
        int e = i >> 4, p = i & 15;
        ws[e][p] = pack2(Qw[(2 * p) * EE + e], Qw[(2 * p + 1) * EE + e]);
    }
    __syncthreads();

    const int rg = tid >> 2;
    const int cg = tid & 3;

    u64 acc[4][4];
#pragma unroll
    for (int r = 0; r < 4; r++)
#pragma unroll
        for (int p = 0; p < 4; p++) acc[r][p] = 0ull;

#pragma unroll
    for (int k4 = 0; k4 < 8; k4++) {
        float xf[4][4];
#pragma unroll
        for (int r = 0; r < 4; r++)
            *(float4*)xf[r] = *(const float4*)&xs[rg + 32 * r][k4 * 4];
#pragma unroll
        for (int kk = 0; kk < 4; kk++) {
            int k = k4 * 4 + kk;
            ulonglong2 wa = *(const ulonglong2*)&ws[k][cg * 4];
            ulonglong2 wb = *(const ulonglong2*)&ws[k][cg * 4 + 2];
#pragma unroll
            for (int r = 0; r < 4; r++) {
                u64 xd = dup2(xf[r][kk]);
                acc[r][0] = ffma2(xd, wa.x, acc[r][0]);
                acc[r][1] = ffma2(xd, wa.y, acc[r][1]);
                acc[r][2] = ffma2(xd, wb.x, acc[r][2]);
                acc[r][3] = ffma2(xd, wb.y, acc[r][3]);
            }
        }
    }

    float part[8];
#pragma unroll
    for (int c = 0; c < 8; c++) part[c] = 0.0f;

#pragma unroll
    for (int r = 0; r < 4; r++) {
        float v[8];
#pragma unroll
        for (int p = 0; p < 4; p++) unpack2(acc[r][p], v[2 * p], v[2 * p + 1]);
#pragma unroll
        for (int c = 0; c < 8; c++) {
            float s = silu_f(v[c]);
            v[c] = s;
            part[c] = fmaf(s, s, part[c]);
        }
        int row = rg + 32 * r;
        float* dst = g_q + base + (size_t)row * EE + cg * 8;
        *(float4*)dst       = make_float4(v[0], v[1], v[2], v[3]);
        *(float4*)(dst + 4) = make_float4(v[4], v[5], v[6], v[7]);
    }
#pragma unroll
    for (int c = 0; c < 8; c++) red[rg][cg * 8 + c] = part[c];
    __syncthreads();

    if (tid < 32) {
        float s = 0.0f;
#pragma unroll
        for (int i = 0; i < 32; i++) s += red[i][tid];
        g_partial[(b * 64 + blk) * EE + tid] = s;
    }
}

// =======================================================================
// K2: reduce 64 block partials -> rnorm. grid 64, block 32. Deterministic.
// =======================================================================
__global__ void k2_norm() {
    const int b = blockIdx.x;
    const int f = threadIdx.x;
    float s = 0.0f;
#pragma unroll
    for (int i = 0; i < 64; i++) s += g_partial[(b * 64 + i) * EE + f];
    g_rnorm[b * EE + f] = 1.0f / fmaxf(sqrtf(s), 1e-12f);
}

// =======================================================================
// K3: h = silu(q @ (rnorm o W1)^T + b1); out = h @ W2^T + b2
// R3's proven 8x8 / 8x4 tiling, 128-row tile, 128 threads — but hs is
// OVERLAID on qs (qs dead after stage-1 k-loop), cutting smem 70->51.6KB
// so 4 blocks/SM (16 warps) fit. grid (64, 64).
// =======================================================================
#define K3_SMEM 51584
__global__ __launch_bounds__(128, 4) void k3_mlp(const float* __restrict__ W1,
                                                 const float* __restrict__ b1,
                                                 const float* __restrict__ W2,
                                                 const float* __restrict__ b2,
                                                 float* __restrict__ out) {
    extern __shared__ __align__(16) char sm[];
    float (*qs)[36]  = (float (*)[36])(sm);                // 18432 B (dies after stage1)
    float (*hs)[68]  = (float (*)[68])(sm);                // 34816 B (overlaid on qs)
    u64   (*w1s)[32] = (u64 (*)[32])(sm + 34816);          // [e][hpair] 8192
    u64   (*w2s)[16] = (u64 (*)[16])(sm + 43008);          // [h][epair] 8192
    u64* b1s = (u64*)(sm + 51200);                         // 256
    u64* b2s = (u64*)(sm + 51456);                         // 128  -> total 51584

    const int tid = threadIdx.x;
    const int b   = blockIdx.y;
    const int blk = blockIdx.x;
    const size_t base = ((size_t)b * SS + (size_t)blk * 128) * EE;

    // --- stage q tile (128 x 32 = 1024 float4) ---
    const float4* qsrc = (const float4*)(g_q + base);
#pragma unroll
    for (int i = 0; i < 8; i++) {
        int idx = tid + i * 128;
        *(float4*)&qs[idx >> 3][(idx & 7) * 4] = qsrc[idx];
    }
    // --- stage W1 * rnorm as pairs along h ---
    const float* W1b = W1 + (size_t)b * HH * EE;
    const float* rn  = g_rnorm + b * EE;
#pragma unroll
    for (int j = 0; j < 8; j++) {
        int i = tid + j * 128;
        int e = i >> 5, hp = i & 31;
        float r = rn[e];
        w1s[e][hp] = pack2(W1b[(2 * hp) * EE + e] * r, W1b[(2 * hp + 1) * EE + e] * r);
    }
    // --- stage W2 as pairs along e ---
    const float* W2b = W2 + (size_t)b * EE * HH;
#pragma unroll
    for (int j = 0; j < 8; j++) {
        int i = tid + j * 128;
        int h = i >> 4, ep = i & 15;
        w2s[h][ep] = pack2(W2b[(2 * ep) * HH + h], W2b[(2 * ep + 1) * HH + h]);
    }
    if (tid < 32) b1s[tid] = pack2(b1[b * HH + 2 * tid], b1[b * HH + 2 * tid + 1]);
    if (tid < 16) b2s[tid] = pack2(b2[b * EE + 2 * tid], b2[b * EE + 2 * tid + 1]);
    __syncthreads();

    const int rg = tid >> 3;   // 16 row-groups, rows rg + 16*r, r<8
    const int cg = tid & 7;

    // ---------------- stage 1: h tile (128 x 64), accs in regs ----------------
    u64 acc[8][4];
#pragma unroll
    for (int r = 0; r < 8; r++)
#pragma unroll
        for (int p = 0; p < 4; p++) acc[r][p] = b1s[cg * 4 + p];

#pragma unroll
    for (int k4 = 0; k4 < 8; k4++) {
        float xf[8][4];
#pragma unroll
        for (int r = 0; r < 8; r++)
            *(float4*)xf[r] = *(const float4*)&qs[rg + 16 * r][k4 * 4];
#pragma unroll
        for (int kk = 0; kk < 4; kk++) {
            int k = k4 * 4 + kk;
            ulonglong2 wa = *(const ulonglong2*)&w1s[k][cg * 4];
            ulonglong2 wb = *(const ulonglong2*)&w1s[k][cg * 4 + 2];
#pragma unroll
            for (int r = 0; r < 8; r++) {
                u64 xd = dup2(xf[r][kk]);
                acc[r][0] = ffma2(xd, wa.x, acc[r][0]);
                acc[r][1] = ffma2(xd, wa.y, acc[r][1]);
                acc[r][2] = ffma2(xd, wb.x, acc[r][2]);
                acc[r][3] = ffma2(xd, wb.y, acc[r][3]);
            }
        }
    }

    // qs fully consumed by ALL threads before hs overlay writes
    __syncthreads();

#pragma unroll
    for (int r = 0; r < 8; r++) {
        float v[8];
#pragma unroll
        for (int p = 0; p < 4; p++) unpack2(acc[r][p], v[2 * p], v[2 * p + 1]);
#pragma unroll
        for (int c = 0; c < 8; c++) v[c] = silu_f(v[c]);
        int row = rg + 16 * r;
        *(float4*)&hs[row][cg * 8]     = make_float4(v[0], v[1], v[2], v[3]);
        *(float4*)&hs[row][cg * 8 + 4] = make_float4(v[4], v[5], v[6], v[7]);
    }
    __syncthreads();

    // ---------------- stage 2: out tile (128 x 32), 8 rows x 4 e-cols ----------------
    {
        u64 oacc[8][2];
#pragma unroll
        for (int r = 0; r < 8; r++) {
            oacc[r][0] = b2s[cg * 2];
            oacc[r][1] = b2s[cg * 2 + 1];
        }

#pragma unroll
        for (int k4 = 0; k4 < 16; k4++) {
            float xf[8][4];
#pragma unroll
            for (int r = 0; r < 8; r++)
                *(float4*)xf[r] = *(const float4*)&hs[rg + 16 * r][k4 * 4];
#pragma unroll
            for (int kk = 0; kk < 4; kk++) {
                int k = k4 * 4 + kk;
                ulonglong2 w = *(const ulonglong2*)&w2s[k][cg * 2];
#pragma unroll
                for (int r = 0; r < 8; r++) {
                    u64 xd = dup2(xf[r][kk]);
                    oacc[r][0] = ffma2(xd, w.x, oacc[r][0]);
                    oacc[r][1] = ffma2(xd, w.y, oacc[r][1]);
                }
            }
        }
#pragma unroll
        for (int r = 0; r < 8; r++) {
            float v[4];
            unpack2(oacc[r][0], v[0], v[1]);
            unpack2(oacc[r][1], v[2], v[3]);
            int row = rg + 16 * r;
            *(float4*)(out + base + (size_t)row * EE + cg * 4) =
                make_float4(v[0], v[1], v[2], v[3]);
        }
    }
}

// =======================================================================
extern "C" void kernel_launch(void* const* d_in, const int* in_sizes, int n_in,
                              void* d_out, int out_size) {
    const float* x  = (const float*)d_in[0];
    const float* Qw = (const float*)d_in[1];
    const float* W1 = (const float*)d_in[2];
    const float* b1 = (const float*)d_in[3];
    const float* W2 = (const float*)d_in[4];
    const float* b2 = (const float*)d_in[5];
    float* out = (float*)d_out;

    // host-side attribute set; runs during capture only
    cudaFuncSetAttribute(k3_mlp, cudaFuncAttributeMaxDynamicSharedMemorySize, K3_SMEM);

    k1_proj<<<dim3(SS / 128, BB), 128>>>(x, Qw);
    k2_norm<<<BB, 32>>>();
    k3_mlp<<<dim3(SS / 128, BB), 128, K3_SMEM>>>(W1, b1, W2, b2, out);
}